// round 15
// baseline (speedup 1.0000x reference)
#include <cuda_runtime.h>
#include <math.h>
#include <stdint.h>

#define B_    8
#define CIN_  128
#define N_    2048
#define K_    16
#define G_    4
#define L_    192
#define NL_   64
#define CL_   48
#define CNL_  16
#define COUT_ 256
#define TN    8       // n-tile per CTA in k_local
#define THR   512
#define TNL   64      // n-tile per CTA in k_nl_main

// ---------------- tf32 rounding (emulate cuBLAS TF32 operand conversion) ----------------
__device__ __forceinline__ float tf32r(float a) {
    uint32_t u;
    asm("cvt.rna.tf32.f32 %0, %1;" : "=r"(u) : "f"(a));
    return __uint_as_float(u);
}

// ---------------- scratch (device globals) ----------------
__device__ float g_cent[B_ * G_ * N_];
__device__ float g_vals[B_ * G_ * K_];
__device__ int   g_inds[B_ * G_ * K_];
__device__ float g_M[B_ * G_ * CNL_ * K_];
__device__ float g_nv2j[B_ * G_ * CNL_ * K_];
__device__ float g_tanhvals[B_ * G_ * K_];

// pre-rounded (tf32) weights in access-optimal layouts
__device__ float  rT_Wq[64 * L_];     // [c][o]
__device__ float  r_Wk[L_ * 64];      // [o][cc]
__device__ float  rT_Wv[CIN_ * L_];   // [cc][o]
__device__ float  rT_pe_w2[L_ * L_];  // [c][d]
__device__ float4 g_w1pack[L_];       // {w1x,w1y,w1z,b1}
__device__ float  rT_Wnq[64 * NL_];
__device__ float  rT_Wnk[64 * NL_];
__device__ float  rT_Wnv1[64 * NL_];
__device__ float  rT_Wnv2[64 * NL_];
__device__ float  r_npe_w1[G_ * 3 * CNL_];
__device__ float  r_npe_w2[G_ * CNL_ * CNL_];

// ---------------- kernel: round/transpose weights, zero cent ----------------
__global__ void k_prep(const float* __restrict__ Wq, const float* __restrict__ Wk,
                       const float* __restrict__ Wv,
                       const float* __restrict__ pe_w1, const float* __restrict__ pe_b1,
                       const float* __restrict__ pe_w2,
                       const float* __restrict__ Wnq, const float* __restrict__ Wnk,
                       const float* __restrict__ Wnv1, const float* __restrict__ Wnv2,
                       const float* __restrict__ npe_w1, const float* __restrict__ npe_w2) {
    int tid = blockIdx.x * blockDim.x + threadIdx.x;
    int nth = gridDim.x * blockDim.x;
    for (int i = tid; i < 64 * L_; i += nth) {
        int c = i / L_, o = i % L_;
        rT_Wq[i] = tf32r(Wq[o * 64 + c]);
    }
    for (int i = tid; i < L_ * 64; i += nth) r_Wk[i] = tf32r(Wk[i]);
    for (int i = tid; i < CIN_ * L_; i += nth) {
        int c = i / L_, o = i % L_;
        rT_Wv[i] = tf32r(Wv[o * CIN_ + c]);
    }
    for (int i = tid; i < L_ * L_; i += nth) {
        int c = i / L_, d = i % L_;
        rT_pe_w2[i] = tf32r(pe_w2[d * L_ + c]);
    }
    for (int d = tid; d < L_; d += nth) {
        g_w1pack[d] = make_float4(tf32r(pe_w1[d]), tf32r(pe_w1[L_ + d]),
                                  tf32r(pe_w1[2 * L_ + d]), pe_b1[d]);
    }
    for (int i = tid; i < 64 * NL_; i += nth) {
        int c = i / NL_, o = i % NL_;
        rT_Wnq[i]  = tf32r(Wnq[o * 64 + c]);
        rT_Wnk[i]  = tf32r(Wnk[o * 64 + c]);
        rT_Wnv1[i] = tf32r(Wnv1[o * 64 + c]);
        rT_Wnv2[i] = tf32r(Wnv2[o * 64 + c]);
    }
    for (int i = tid; i < G_ * 3 * CNL_; i += nth)    r_npe_w1[i] = tf32r(npe_w1[i]);
    for (int i = tid; i < G_ * CNL_ * CNL_; i += nth) r_npe_w2[i] = tf32r(npe_w2[i]);
    for (int i = tid; i < B_ * G_ * N_; i += nth) g_cent[i] = 0.f;
}

// ---------------- k_local smem (TN=8, THR=512) ----------------
#define XPAD  129     // x row pad (odd -> conflict-free column access)
#define QPAD  36      // qt/kt row pad: multiple of 4 -> aligned float4 reads in D
#define LPAD  12      // lq row pad: 48B, float4-aligned at offsets 0/16B
#define XAPAD 12      // xa row pad (overlays qt+kt+lq)

struct __align__(16) LocalSmem {
    float x[CIN_ * XPAD];        // raw x tile, 66048 B
    float qt[96 * QPAD];         // [dloc][n*4+g], 13824 B (xa overlay starts here)
    float kt[64 * QPAD];         // [cc][n*4+g], 9216 B
    float lq[L_ * LPAD];         // [o][n], 9216 B
    float absx[64][TN];          // 2048 B
    float rel[TN][K_][4];        // 2048 B
    float part[4][G_][TN][K_];   // 8192 B
    float att[G_][TN][K_];       // raw att, 2048 B
    float bconst[G_][TN];        // 128 B
    int   idxs[TN][K_];          // 512 B
};                               // total 113280 B

// ---------------- kernel 1: fused local branch (regrouped, 32 warps/SM) ----------------
__global__ __launch_bounds__(THR) void k_local(
    const float* __restrict__ x,
    const float* __restrict__ abs_x,
    const float* __restrict__ points,
    const float* __restrict__ pe_b2,
    const int*   __restrict__ idx,
    float*       __restrict__ out)
{
    extern __shared__ char smem_raw[];
    LocalSmem* s = (LocalSmem*)smem_raw;

    const int blk = blockIdx.x;
    const int b   = blk >> 8;              // / 256
    const int n0  = (blk & 255) * TN;
    const int tid = threadIdx.x;

    // ================= phase A: loads =================
    {
        const float* xb = x + ((size_t)(b * CIN_) * N_ + n0) * K_;
        for (int i = tid; i < CIN_ * 32; i += THR) {   // 32 float4 per cc row
            int cc = i >> 5, q = i & 31;
            float4 v = *(const float4*)(xb + (size_t)cc * N_ * K_ + q * 4);
            float* dst = &s->x[cc * XPAD + q * 4];
            dst[0] = v.x; dst[1] = v.y; dst[2] = v.z; dst[3] = v.w;
        }
        if (tid < 64 * TN) {
            int c = tid >> 3, n = tid & 7;
            s->absx[c][n] = tf32r(abs_x[(b * 64 + c) * N_ + n0 + n]);
        }
        if (tid < TN * K_) {
            int n = tid >> 4, k = tid & 15;
            s->idxs[n][k] = idx[(b * N_ + n0 + n) * K_ + k];
        }
    }
    __syncthreads();

    // ================= phase B: lq (384 thr, 4n each) + rel gather (128 thr) =================
    if (tid < 384) {
        const int o = tid % 192, nh = tid / 192;
        float a0 = 0.f, a1 = 0.f, a2 = 0.f, a3 = 0.f;
        #pragma unroll 8
        for (int c = 0; c < 64; c++) {
            float w = rT_Wq[c * L_ + o];
            float4 av = *(const float4*)&s->absx[c][nh * 4];
            a0 += w * av.x; a1 += w * av.y; a2 += w * av.z; a3 += w * av.w;
        }
        *(float4*)&s->lq[o * LPAD + nh * 4] = make_float4(a0, a1, a2, a3);
    } else {
        int t = tid - 384;
        for (int r = t; r < 3 * TN * K_; r += 128) {     // 384 elems
            int ax = r >> 7, rem = r & 127, n = rem >> 4, k = rem & 15;
            float p  = points[(b * 3 + ax) * N_ + s->idxs[n][k]];
            float p0 = points[(b * 3 + ax) * N_ + s->idxs[n][0]];
            s->rel[n][k][ax] = tf32r(p - p0);
        }
    }
    __syncthreads();

    // ---- qt task: (g, dloc) -> all 8 n, weights read once ----
    auto qt_task8 = [&](int g, int dloc, int dbase) {
        int d = dbase + dloc;
        float a0 = 0.f, a1 = 0.f, a2 = 0.f, a3 = 0.f;
        float a4 = 0.f, a5 = 0.f, a6 = 0.f, a7 = 0.f;
        const float* wcol = &rT_pe_w2[(g * CL_) * L_ + d];
        #pragma unroll 8
        for (int c = 0; c < CL_; c++) {
            float w = wcol[c * L_];
            const float4* lp = (const float4*)&s->lq[(g * CL_ + c) * LPAD];
            float4 l0 = lp[0], l1 = lp[1];
            a0 += w * l0.x; a1 += w * l0.y; a2 += w * l0.z; a3 += w * l0.w;
            a4 += w * l1.x; a5 += w * l1.y; a6 += w * l1.z; a7 += w * l1.w;
        }
        float* qp = &s->qt[dloc * QPAD + g];
        qp[0]  = a0; qp[4]  = a1; qp[8]  = a2; qp[12] = a3;
        qp[16] = a4; qp[20] = a5; qp[24] = a6; qp[28] = a7;
    };
    // ---- kt task: (g, cc) -> all 8 n ----
    auto kt_task8 = [&](int g, int cc) {
        float a0 = 0.f, a1 = 0.f, a2 = 0.f, a3 = 0.f;
        float a4 = 0.f, a5 = 0.f, a6 = 0.f, a7 = 0.f;
        #pragma unroll 8
        for (int c = 0; c < CL_; c++) {
            float w = r_Wk[(g * CL_ + c) * 64 + cc];
            const float4* lp = (const float4*)&s->lq[(g * CL_ + c) * LPAD];
            float4 l0 = lp[0], l1 = lp[1];
            a0 += w * l0.x; a1 += w * l0.y; a2 += w * l0.z; a3 += w * l0.w;
            a4 += w * l1.x; a5 += w * l1.y; a6 += w * l1.z; a7 += w * l1.w;
        }
        float* kp = &s->kt[cc * QPAD + g];
        kp[0]  = a0; kp[4]  = a1; kp[8]  = a2; kp[12] = a3;
        kp[16] = a4; kp[20] = a5; kp[24] = a6; kp[28] = a7;
    };

    // ================= phase C0: qt(d<96) [384] + kt(cc<32) [128] = 512 exact =================
    if (tid < 384) {
        qt_task8(tid / 96, tid % 96, 0);
    } else {
        int t2 = tid - 384;                   // 0..127
        kt_task8(t2 >> 5, t2 & 31);
    }
    __syncthreads();

    // ================= phase D0: spe(d<96, quarter per dq) + S_k(cc<32, 8 per dq) =================
    {
        int dq = tid >> 7;                    // 0..3
        int r = tid & 127, n = r >> 4, k = r & 15;
        float rx = s->rel[n][k][0], ry = s->rel[n][k][1], rz = s->rel[n][k][2];
        float a0 = 0.f, a1 = 0.f, a2 = 0.f, a3 = 0.f;
        #pragma unroll 4
        for (int dd = 0; dd < 24; dd++) {
            int d = dq * 24 + dd;
            float4 wp = g_w1pack[d];
            float hv = rx * wp.x + ry * wp.y + rz * wp.z + wp.w;
            hv = hv > 0.f ? hv : 0.f;
            hv = tf32r(hv);
            float4 q4 = *(const float4*)&s->qt[d * QPAD + n * 4];
            a0 += q4.x * hv; a1 += q4.y * hv; a2 += q4.z * hv; a3 += q4.w * hv;
        }
        #pragma unroll 4
        for (int cc = dq * 8; cc < dq * 8 + 8; cc++) {   // cc 0..31 only (kt from C0)
            float xsv = tf32r(s->x[cc * XPAD + n * 16 + k]
                            + s->x[(cc + 64) * XPAD + n * 16 + k]);
            float4 k4 = *(const float4*)&s->kt[cc * QPAD + n * 4];
            a0 += k4.x * xsv; a1 += k4.y * xsv; a2 += k4.z * xsv; a3 += k4.w * xsv;
        }
        s->part[dq][0][n][k] = a0; s->part[dq][1][n][k] = a1;
        s->part[dq][2][n][k] = a2; s->part[dq][3][n][k] = a3;
    }
    __syncthreads();

    // ================= phase C1: qt(d>=96) [384] + kt(cc>=32) [128] + bconst [32] =================
    for (int t = tid; t < 544; t += THR) {
        if (t < 384) {
            qt_task8(t / 96, t % 96, 96);
        } else if (t < 512) {
            int t2 = t - 384;
            kt_task8(t2 >> 5, 32 + (t2 & 31));
        } else {
            int t3 = t - 512;                 // 0..31
            int g = t3 >> 3, n = t3 & 7;
            float sum = 0.f;
            #pragma unroll 8
            for (int c = 0; c < CL_; c++)
                sum += s->lq[(g * CL_ + c) * LPAD + n] * pe_b2[g * CL_ + c];
            s->bconst[g][n] = sum;
        }
    }
    __syncthreads();

    // ================= phase D1: spe(d>=96) + S_k(cc>=32, 8 per dq), accumulate =================
    {
        int dq = tid >> 7;
        int r = tid & 127, n = r >> 4, k = r & 15;
        float rx = s->rel[n][k][0], ry = s->rel[n][k][1], rz = s->rel[n][k][2];
        float a0 = 0.f, a1 = 0.f, a2 = 0.f, a3 = 0.f;
        #pragma unroll 4
        for (int dd = 0; dd < 24; dd++) {
            int dloc = dq * 24 + dd;
            float4 wp = g_w1pack[96 + dloc];
            float hv = rx * wp.x + ry * wp.y + rz * wp.z + wp.w;
            hv = hv > 0.f ? hv : 0.f;
            hv = tf32r(hv);
            float4 q4 = *(const float4*)&s->qt[dloc * QPAD + n * 4];
            a0 += q4.x * hv; a1 += q4.y * hv; a2 += q4.z * hv; a3 += q4.w * hv;
        }
        #pragma unroll 4
        for (int cc = 32 + dq * 8; cc < 32 + dq * 8 + 8; cc++) {  // cc 32..63 (kt from C1)
            float xsv = tf32r(s->x[cc * XPAD + n * 16 + k]
                            + s->x[(cc + 64) * XPAD + n * 16 + k]);
            float4 k4 = *(const float4*)&s->kt[cc * QPAD + n * 4];
            a0 += k4.x * xsv; a1 += k4.y * xsv; a2 += k4.z * xsv; a3 += k4.w * xsv;
        }
        s->part[dq][0][n][k] += a0; s->part[dq][1][n][k] += a1;
        s->part[dq][2][n][k] += a2; s->part[dq][3][n][k] += a3;
    }
    __syncthreads();

    // ================= phase E: combine + softmax (32 tasks) =================
    if (tid < G_ * TN) {
        int g = tid >> 3, n = tid & 7;
        float sc[K_];
        float m = -1e30f;
        #pragma unroll
        for (int k = 0; k < K_; k++) {
            sc[k] = s->part[0][g][n][k] + s->part[1][g][n][k]
                  + s->part[2][g][n][k] + s->part[3][g][n][k] + s->bconst[g][n];
            m = fmaxf(m, sc[k]);
        }
        float sum = 0.f;
        #pragma unroll
        for (int k = 0; k < K_; k++) { sc[k] = expf(sc[k] - m); sum += sc[k]; }
        float inv = 1.f / sum;
        #pragma unroll
        for (int k = 0; k < K_; k++) s->att[g][n][k] = sc[k] * inv;
    }
    __syncthreads();

    // ================= phase F: scatter (1 atomic/thread) + xa =================
    {
        {
            int g = tid >> 7, rem = tid & 127, n = rem >> 4, k = rem & 15;
            atomicAdd(&g_cent[(b * G_ + g) * N_ + s->idxs[n][k]], s->att[g][n][k]);
        }
        float* xa = &s->qt[0];   // overlays qt+kt+lq (32256B >= 512*12*4=24576B)
        int cc = tid & 127, nset = tid >> 7;              // nset 0..3, 2 n each
        for (int ni = 0; ni < 2; ni++) {
            int n = nset * 2 + ni;
            float a0 = 0.f, a1 = 0.f, a2 = 0.f, a3 = 0.f;
            #pragma unroll
            for (int k = 0; k < K_; k++) {
                float xv = tf32r(s->x[cc * XPAD + n * 16 + k]);
                a0 += tf32r(s->att[0][n][k]) * xv;
                a1 += tf32r(s->att[1][n][k]) * xv;
                a2 += tf32r(s->att[2][n][k]) * xv;
                a3 += tf32r(s->att[3][n][k]) * xv;
            }
            xa[(0 * CIN_ + cc) * XAPAD + n] = a0;
            xa[(1 * CIN_ + cc) * XAPAD + n] = a1;
            xa[(2 * CIN_ + cc) * XAPAD + n] = a2;
            xa[(3 * CIN_ + cc) * XAPAD + n] = a3;
        }
    }
    __syncthreads();

    // ================= phase G: out = Wv^T-dot(xa) (384 thr, 4n each) + direct store =================
    if (tid < 384) {
        const float* xa = &s->qt[0];
        int o = tid % 192, nh = tid / 192;
        int g = o / CL_;
        float a0 = 0.f, a1 = 0.f, a2 = 0.f, a3 = 0.f;
        #pragma unroll 8
        for (int cc = 0; cc < CIN_; cc++) {
            float w = rT_Wv[cc * L_ + o];
            float4 xv = *(const float4*)&xa[(g * CIN_ + cc) * XAPAD + nh * 4];
            a0 += w * xv.x; a1 += w * xv.y; a2 += w * xv.z; a3 += w * xv.w;
        }
        *(float4*)&out[((size_t)(b * COUT_ + o)) * N_ + n0 + nh * 4] =
            make_float4(a0, a1, a2, a3);
    }
}

// ---------------- kernel 2: top-16 per (b,g), desc, tie -> lower index ----------------
__global__ __launch_bounds__(256) void k_topk() {
    const int bg  = blockIdx.x;
    const int tid = threadIdx.x;
    const int lane = tid & 31, warp = tid >> 5;
    __shared__ float v_s[N_];
    __shared__ float wvv[8];
    __shared__ int   wii[8];

    for (int i = tid; i < N_; i += 256) v_s[i] = g_cent[bg * N_ + i];
    __syncthreads();

    for (int t = 0; t < K_; t++) {
        float bv = -1e30f; int bi = N_;
        for (int i = tid; i < N_; i += 256) {
            float v = v_s[i];
            if (v > bv || (v == bv && i < bi)) { bv = v; bi = i; }
        }
        #pragma unroll
        for (int off = 16; off > 0; off >>= 1) {
            float ov = __shfl_down_sync(0xffffffffu, bv, off);
            int   oi = __shfl_down_sync(0xffffffffu, bi, off);
            if (ov > bv || (ov == bv && oi < bi)) { bv = ov; bi = oi; }
        }
        if (lane == 0) { wvv[warp] = bv; wii[warp] = bi; }
        __syncthreads();
        if (tid < 32) {
            float v2 = (tid < 8) ? wvv[tid] : -1e30f;
            int   i2 = (tid < 8) ? wii[tid] : N_;
            #pragma unroll
            for (int off = 4; off > 0; off >>= 1) {
                float ov = __shfl_down_sync(0xffffffffu, v2, off);
                int   oi = __shfl_down_sync(0xffffffffu, i2, off);
                if (ov > v2 || (ov == v2 && oi < i2)) { v2 = ov; i2 = oi; }
            }
            if (tid == 0) {
                g_vals[bg * K_ + t] = v2;
                g_inds[bg * K_ + t] = i2;
                v_s[i2] = -1e30f;
            }
        }
        __syncthreads();
    }
}

// ---------------- kernel 3: non-local prep per (b,g), smem-staged gathers ----------------
__global__ __launch_bounds__(256) void k_nl_prep(
    const float* __restrict__ abs_x,
    const float* __restrict__ points,
    const float* __restrict__ npe_b1,
    const float* __restrict__ npe_b2)
{
    const int bg = blockIdx.x;
    const int b = bg / G_, g = bg % G_;
    const int tid = threadIdx.x;

    __shared__ int   inds_s[K_];
    __shared__ float rel_s[3][K_];
    __shared__ float h2_s[K_][CNL_];
    __shared__ float a2g[K_][65];     // gathered tf32r(abs_x) at selected indices

    if (tid < K_) {
        inds_s[tid] = g_inds[bg * K_ + tid];
        g_tanhvals[bg * K_ + tid] = tanhf(g_vals[bg * K_ + tid]);
    }
    __syncthreads();
    // gather abs_x columns for the 16 selected n (4 LDG per thread)
    for (int i = tid; i < K_ * 64; i += 256) {
        int j = i >> 6, cc = i & 63;
        a2g[j][cc] = tf32r(abs_x[(b * 64 + cc) * N_ + inds_s[j]]);
    }
    if (tid < 3 * K_) {
        int c = tid / K_, j = tid % K_;
        rel_s[c][j] = tf32r(points[(b * 3 + c) * N_ + inds_s[j]]
                          - points[(b * 3 + c) * N_ + inds_s[0]]);
    }
    __syncthreads();
    {
        int j = tid / CNL_, d = tid % CNL_;
        float h = npe_b1[g * CNL_ + d];
        #pragma unroll
        for (int c = 0; c < 3; c++) h += rel_s[c][j] * r_npe_w1[(g * 3 + c) * CNL_ + d];
        h2_s[j][d] = tf32r(h > 0.f ? h : 0.f);
    }
    __syncthreads();
    {
        int c = tid / K_, j = tid % K_;
        float pe = npe_b2[g * CNL_ + c];
        #pragma unroll
        for (int d = 0; d < CNL_; d++) pe += h2_s[j][d] * r_npe_w2[(g * CNL_ + d) * CNL_ + c];
        float nk = 0.f, nv2 = 0.f;
        const int row = g * CNL_ + c;
        #pragma unroll 8
        for (int cc = 0; cc < 64; cc++) {
            float a = a2g[j][cc];
            nk  += rT_Wnk[cc * NL_ + row]  * a;
            nv2 += rT_Wnv2[cc * NL_ + row] * a;
        }
        g_M[bg * CNL_ * K_ + c * K_ + j]    = nk + pe;
        g_nv2j[bg * CNL_ * K_ + c * K_ + j] = nv2;
    }
}

// ---------------- kernel 4: non-local main (full a2 preload, barrier-free loop) ----------------
struct __align__(16) NLSmem {
    float wnq[64 * 64];
    float wnv1[64 * 64];
    float wnv2[64 * 64];
    float M[G_][CNL_ * K_];
    float nv2jT[G_][K_ * CNL_];
    float tv[G_ * K_];
    float a2[64][TNL];           // [cc][n_local], 16 KB
    float outbuf[64 * 65];
};                               // ~90.6 KB -> 2 CTA/SM

__global__ __launch_bounds__(256) void k_nl_main(
    const float* __restrict__ abs_x,
    float*       __restrict__ out)
{
    extern __shared__ char smraw[];
    NLSmem* s = (NLSmem*)smraw;

    const int blk = blockIdx.x;
    const int b   = blk / (N_ / TNL);
    const int n0  = (blk % (N_ / TNL)) * TNL;
    const int tid = threadIdx.x;
    const int warp  = tid >> 5;
    const int half  = (tid >> 4) & 1;
    const int c     = tid & 15;
    const int g     = (warp & 1) * 2 + half;
    const int nslot = warp >> 1;
    const int o     = g * CNL_ + c;

    for (int i = tid; i < 64 * 64; i += 256) {
        s->wnq[i]  = rT_Wnq[i];
        s->wnv1[i] = rT_Wnv1[i];
        s->wnv2[i] = rT_Wnv2[i];
    }
    for (int i = tid; i < 64 * TNL; i += 256) {   // coalesced a2 preload
        int cc = i >> 6, n = i & 63;
        s->a2[cc][n] = tf32r(abs_x[(b * 64 + cc) * N_ + n0 + n]);
    }
    for (int i = tid; i < G_ * CNL_ * K_; i += 256) {
        float mv = tf32r(g_M[b * G_ * CNL_ * K_ + i]);
        s->M[0][i] = mv;
        int gg = i >> 8, rem = i & 255, cc2 = rem >> 4, jj = rem & 15;
        s->nv2jT[gg][jj * 16 + cc2] = tf32r(g_nv2j[b * G_ * CNL_ * K_ + i]);
    }
    if (tid < G_ * K_) s->tv[tid] = g_tanhvals[b * G_ * K_ + tid];
    __syncthreads();

    const float tvj = s->tv[g * K_ + c];

    for (int it = 0; it < TNL / 4; it++) {
        const int nn = it * 4 + nslot;

        float nq = 0.f, nv1 = 0.f, nv2 = 0.f;
        #pragma unroll 8
        for (int cc = 0; cc < 64; cc++) {
            float a = s->a2[cc][nn];
            nq  += s->wnq[cc * 64 + o]  * a;
            nv1 += s->wnv1[cc * 64 + o] * a;
            nv2 += s->wnv2[cc * 64 + o] * a;
        }
        float nqr = tf32r(nq);

        float sc = 0.f;
        const float* Mg = s->M[g];
        #pragma unroll
        for (int c2 = 0; c2 < CNL_; c2++) {
            float v = __shfl_sync(0xffffffffu, nqr, c2, 16);
            sc += v * Mg[c2 * 16 + c];
        }
        float m = -1e30f;
        #pragma unroll
        for (int j = 0; j < K_; j++) m = fmaxf(m, __shfl_sync(0xffffffffu, sc, j, 16));
        float e = expf(sc - m);
        float sum = 0.f;
        #pragma unroll
        for (int j = 0; j < K_; j++) sum += __shfl_sync(0xffffffffu, e, j, 16);
        float inv = 1.f / sum;
        float w = e * inv * tvj;
        float ws = 0.f;
        #pragma unroll
        for (int j = 0; j < K_; j++) ws += __shfl_sync(0xffffffffu, w, j, 16);

        float og = (nv1 - nv2) * ws;
        const float* nvg = s->nv2jT[g];
        #pragma unroll
        for (int j = 0; j < K_; j++) {
            float wj = tf32r(__shfl_sync(0xffffffffu, w, j, 16));
            og += wj * nvg[j * 16 + c];
        }
        s->outbuf[o * 65 + nn] = og;
    }
    __syncthreads();

    for (int t = tid; t < 64 * 16; t += 256) {
        int o2 = t >> 4, q = t & 15;
        const float* rp = &s->outbuf[o2 * 65 + q * 4];
        float4 v = make_float4(rp[0], rp[1], rp[2], rp[3]);
        *(float4*)&out[((size_t)(b * COUT_ + L_ + o2)) * N_ + n0 + q * 4] = v;
    }
}

// ---------------- launcher ----------------
extern "C" void kernel_launch(void* const* d_in, const int* in_sizes, int n_in,
                              void* d_out, int out_size) {
    const float* x      = (const float*)d_in[0];
    const float* abs_x  = (const float*)d_in[1];
    const float* points = (const float*)d_in[2];
    const float* Wq     = (const float*)d_in[3];
    const float* Wk     = (const float*)d_in[4];
    const float* Wv     = (const float*)d_in[5];
    const float* Wnq    = (const float*)d_in[6];
    const float* Wnk    = (const float*)d_in[7];
    const float* Wnv1   = (const float*)d_in[8];
    const float* Wnv2   = (const float*)d_in[9];
    const float* pe_w1  = (const float*)d_in[10];
    const float* pe_b1  = (const float*)d_in[11];
    const float* pe_w2  = (const float*)d_in[12];
    const float* pe_b2  = (const float*)d_in[13];
    const float* npe_w1 = (const float*)d_in[14];
    const float* npe_b1 = (const float*)d_in[15];
    const float* npe_w2 = (const float*)d_in[16];
    const float* npe_b2 = (const float*)d_in[17];
    const int*   idx    = (const int*)d_in[18];
    float* out = (float*)d_out;

    static int smem_set = 0;
    if (!smem_set) {
        cudaFuncSetAttribute(k_local, cudaFuncAttributeMaxDynamicSharedMemorySize,
                             (int)sizeof(LocalSmem));
        cudaFuncSetAttribute(k_nl_main, cudaFuncAttributeMaxDynamicSharedMemorySize,
                             (int)sizeof(NLSmem));
        smem_set = 1;
    }

    k_prep<<<128, 256>>>(Wq, Wk, Wv, pe_w1, pe_b1, pe_w2,
                         Wnq, Wnk, Wnv1, Wnv2, npe_w1, npe_w2);
    k_local<<<B_ * (N_ / TN), THR, sizeof(LocalSmem)>>>(x, abs_x, points,
                                                        pe_b2, idx, out);
    k_topk<<<B_ * G_, 256>>>();
    k_nl_prep<<<B_ * G_, 256>>>(abs_x, points, npe_b1, npe_b2);
    k_nl_main<<<B_ * (N_ / TNL), 256, sizeof(NLSmem)>>>(abs_x, out);
}

// round 16
// speedup vs baseline: 1.0656x; 1.0656x over previous
#include <cuda_runtime.h>
#include <math.h>
#include <stdint.h>

#define B_    8
#define CIN_  128
#define N_    2048
#define K_    16
#define G_    4
#define L_    192
#define NL_   64
#define CL_   48
#define CNL_  16
#define COUT_ 256
#define TN    8       // n-tile per CTA in k_local
#define THR   512
#define TNL   64      // n-tile per CTA in k_nl_main

// ---------------- tf32 rounding (emulate cuBLAS TF32 operand conversion) ----------------
__device__ __forceinline__ float tf32r(float a) {
    uint32_t u;
    asm("cvt.rna.tf32.f32 %0, %1;" : "=r"(u) : "f"(a));
    return __uint_as_float(u);
}

// ---------------- scratch (device globals) ----------------
__device__ float g_cent[B_ * G_ * N_];
__device__ float g_vals[B_ * G_ * K_];
__device__ int   g_inds[B_ * G_ * K_];
__device__ float g_M[B_ * G_ * CNL_ * K_];
__device__ float g_nv2j[B_ * G_ * CNL_ * K_];
__device__ float g_tanhvals[B_ * G_ * K_];

// pre-rounded (tf32) weights in access-optimal layouts
__device__ float  rT_Wq[64 * L_];     // [c][o]
__device__ float  r_Wk[L_ * 64];      // [o][cc]
__device__ float  rT_Wv[CIN_ * L_];   // [cc][o]
__device__ float  rT_pe_w2[L_ * L_];  // [c][d]
__device__ float4 g_w1pack[L_];       // {w1x,w1y,w1z,b1}
__device__ float  rT_Wnq[64 * NL_];
__device__ float  rT_Wnk[64 * NL_];
__device__ float  rT_Wnv1[64 * NL_];
__device__ float  rT_Wnv2[64 * NL_];
__device__ float  r_npe_w1[G_ * 3 * CNL_];
__device__ float  r_npe_w2[G_ * CNL_ * CNL_];

// ---------------- kernel: round/transpose weights, zero cent ----------------
__global__ void k_prep(const float* __restrict__ Wq, const float* __restrict__ Wk,
                       const float* __restrict__ Wv,
                       const float* __restrict__ pe_w1, const float* __restrict__ pe_b1,
                       const float* __restrict__ pe_w2,
                       const float* __restrict__ Wnq, const float* __restrict__ Wnk,
                       const float* __restrict__ Wnv1, const float* __restrict__ Wnv2,
                       const float* __restrict__ npe_w1, const float* __restrict__ npe_w2) {
    int tid = blockIdx.x * blockDim.x + threadIdx.x;
    int nth = gridDim.x * blockDim.x;
    for (int i = tid; i < 64 * L_; i += nth) {
        int c = i / L_, o = i % L_;
        rT_Wq[i] = tf32r(Wq[o * 64 + c]);
    }
    for (int i = tid; i < L_ * 64; i += nth) r_Wk[i] = tf32r(Wk[i]);
    for (int i = tid; i < CIN_ * L_; i += nth) {
        int c = i / L_, o = i % L_;
        rT_Wv[i] = tf32r(Wv[o * CIN_ + c]);
    }
    for (int i = tid; i < L_ * L_; i += nth) {
        int c = i / L_, d = i % L_;
        rT_pe_w2[i] = tf32r(pe_w2[d * L_ + c]);
    }
    for (int d = tid; d < L_; d += nth) {
        g_w1pack[d] = make_float4(tf32r(pe_w1[d]), tf32r(pe_w1[L_ + d]),
                                  tf32r(pe_w1[2 * L_ + d]), pe_b1[d]);
    }
    for (int i = tid; i < 64 * NL_; i += nth) {
        int c = i / NL_, o = i % NL_;
        rT_Wnq[i]  = tf32r(Wnq[o * 64 + c]);
        rT_Wnk[i]  = tf32r(Wnk[o * 64 + c]);
        rT_Wnv1[i] = tf32r(Wnv1[o * 64 + c]);
        rT_Wnv2[i] = tf32r(Wnv2[o * 64 + c]);
    }
    for (int i = tid; i < G_ * 3 * CNL_; i += nth)    r_npe_w1[i] = tf32r(npe_w1[i]);
    for (int i = tid; i < G_ * CNL_ * CNL_; i += nth) r_npe_w2[i] = tf32r(npe_w2[i]);
    for (int i = tid; i < B_ * G_ * N_; i += nth) g_cent[i] = 0.f;
}

// ---------------- k_local smem (TN=8, THR=512) ----------------
#define XPAD  129     // x row pad (odd -> conflict-free column access)
#define QPAD  36      // qt/kt row pad: multiple of 4 -> aligned float4 reads in D
#define LPAD  12      // lq row pad: 48B, float4-aligned at offsets 0/16B
#define XAPAD 12      // xa row pad (overlays qt+kt+lq)

struct __align__(16) LocalSmem {
    float x[CIN_ * XPAD];        // raw x tile, 66048 B
    float qt[96 * QPAD];         // [dloc][n*4+g], 13824 B (xa overlay starts here)
    float kt[64 * QPAD];         // [cc][n*4+g], 9216 B
    float lq[L_ * LPAD];         // [o][n], 9216 B
    float absx[64][TN];          // 2048 B
    float rel[TN][K_][4];        // 2048 B
    float part[4][G_][TN][K_];   // 8192 B
    float att[G_][TN][K_];       // raw att, 2048 B
    float bconst[G_][TN];        // 128 B
    int   idxs[TN][K_];          // 512 B
};                               // total 113280 B

// ---------------- kernel 1: fused local branch (regrouped, 32 warps/SM) ----------------
__global__ __launch_bounds__(THR) void k_local(
    const float* __restrict__ x,
    const float* __restrict__ abs_x,
    const float* __restrict__ points,
    const float* __restrict__ pe_b2,
    const int*   __restrict__ idx,
    float*       __restrict__ out)
{
    extern __shared__ char smem_raw[];
    LocalSmem* s = (LocalSmem*)smem_raw;

    const int blk = blockIdx.x;
    const int b   = blk >> 8;              // / 256
    const int n0  = (blk & 255) * TN;
    const int tid = threadIdx.x;

    // ================= phase A: loads =================
    {
        const float* xb = x + ((size_t)(b * CIN_) * N_ + n0) * K_;
        for (int i = tid; i < CIN_ * 32; i += THR) {   // 32 float4 per cc row
            int cc = i >> 5, q = i & 31;
            float4 v = *(const float4*)(xb + (size_t)cc * N_ * K_ + q * 4);
            float* dst = &s->x[cc * XPAD + q * 4];
            dst[0] = v.x; dst[1] = v.y; dst[2] = v.z; dst[3] = v.w;
        }
        if (tid < 64 * TN) {
            int c = tid >> 3, n = tid & 7;
            s->absx[c][n] = tf32r(abs_x[(b * 64 + c) * N_ + n0 + n]);
        }
        if (tid < TN * K_) {
            int n = tid >> 4, k = tid & 15;
            s->idxs[n][k] = idx[(b * N_ + n0 + n) * K_ + k];
        }
    }
    __syncthreads();

    // ================= phase B: lq (384 thr, 4n each) + rel gather (128 thr) =================
    if (tid < 384) {
        const int o = tid % 192, nh = tid / 192;
        float a0 = 0.f, a1 = 0.f, a2 = 0.f, a3 = 0.f;
        #pragma unroll 8
        for (int c = 0; c < 64; c++) {
            float w = rT_Wq[c * L_ + o];
            float4 av = *(const float4*)&s->absx[c][nh * 4];
            a0 += w * av.x; a1 += w * av.y; a2 += w * av.z; a3 += w * av.w;
        }
        *(float4*)&s->lq[o * LPAD + nh * 4] = make_float4(a0, a1, a2, a3);
    } else {
        int t = tid - 384;
        for (int r = t; r < 3 * TN * K_; r += 128) {     // 384 elems
            int ax = r >> 7, rem = r & 127, n = rem >> 4, k = rem & 15;
            float p  = points[(b * 3 + ax) * N_ + s->idxs[n][k]];
            float p0 = points[(b * 3 + ax) * N_ + s->idxs[n][0]];
            s->rel[n][k][ax] = tf32r(p - p0);
        }
    }
    __syncthreads();

    // ---- qt task: (g, dloc, nh) -> 4 n ----
    auto qt_task = [&](int g, int dloc, int nh, int dbase) {
        int d = dbase + dloc;
        float a0 = 0.f, a1 = 0.f, a2 = 0.f, a3 = 0.f;
        const float* wcol = &rT_pe_w2[(g * CL_) * L_ + d];
        #pragma unroll 8
        for (int c = 0; c < CL_; c++) {
            float w = wcol[c * L_];
            float4 lv = *(const float4*)&s->lq[(g * CL_ + c) * LPAD + nh * 4];
            a0 += w * lv.x; a1 += w * lv.y; a2 += w * lv.z; a3 += w * lv.w;
        }
        float* qp = &s->qt[dloc * QPAD + nh * 16 + g];
        qp[0] = a0; qp[4] = a1; qp[8] = a2; qp[12] = a3;
    };
    // ---- kt task: (g, cc, nh) -> 4 n ----
    auto kt_task = [&](int g, int cc, int nh) {
        float a0 = 0.f, a1 = 0.f, a2 = 0.f, a3 = 0.f;
        #pragma unroll 8
        for (int c = 0; c < CL_; c++) {
            float w = r_Wk[(g * CL_ + c) * 64 + cc];
            float4 lv = *(const float4*)&s->lq[(g * CL_ + c) * LPAD + nh * 4];
            a0 += w * lv.x; a1 += w * lv.y; a2 += w * lv.z; a3 += w * lv.w;
        }
        float* kp = &s->kt[cc * QPAD + nh * 16 + g];
        kp[0] = a0; kp[4] = a1; kp[8] = a2; kp[12] = a3;
    };

    // ================= phase C0: qt(d<96) [768] + kt(cc<32) [256] =================
    for (int t = tid; t < 1024; t += THR) {
        if (t < 768) {
            int nh = t & 1, rg = t >> 1;          // rg 0..383
            qt_task(rg / 96, rg % 96, nh, 0);
        } else {
            int t2 = t - 768;                     // 0..255
            int g = t2 >> 6, rem = t2 & 63;
            kt_task(g, rem >> 1, rem & 1);
        }
    }
    __syncthreads();

    // ================= phase D0: spe(d<96, quarter per dq) + S_k(cc<32, 8 per dq) =================
    {
        int dq = tid >> 7;                        // 0..3
        int r = tid & 127, n = r >> 4, k = r & 15;
        float rx = s->rel[n][k][0], ry = s->rel[n][k][1], rz = s->rel[n][k][2];
        float a0 = 0.f, a1 = 0.f, a2 = 0.f, a3 = 0.f;
        #pragma unroll 4
        for (int dd = 0; dd < 24; dd++) {
            int d = dq * 24 + dd;
            float4 wp = g_w1pack[d];
            float hv = rx * wp.x + ry * wp.y + rz * wp.z + wp.w;
            hv = hv > 0.f ? hv : 0.f;
            hv = tf32r(hv);
            float4 q4 = *(const float4*)&s->qt[d * QPAD + n * 4];
            a0 += q4.x * hv; a1 += q4.y * hv; a2 += q4.z * hv; a3 += q4.w * hv;
        }
        #pragma unroll 4
        for (int cc = dq * 8; cc < dq * 8 + 8; cc++) {   // cc 0..31 only (kt from C0)
            float xsv = tf32r(s->x[cc * XPAD + n * 16 + k]
                            + s->x[(cc + 64) * XPAD + n * 16 + k]);
            float4 k4 = *(const float4*)&s->kt[cc * QPAD + n * 4];
            a0 += k4.x * xsv; a1 += k4.y * xsv; a2 += k4.z * xsv; a3 += k4.w * xsv;
        }
        s->part[dq][0][n][k] = a0; s->part[dq][1][n][k] = a1;
        s->part[dq][2][n][k] = a2; s->part[dq][3][n][k] = a3;
    }
    __syncthreads();

    // ================= phase C1: qt(d>=96) [768] + kt(cc>=32) [256] + bconst [32] =================
    for (int t = tid; t < 1056; t += THR) {
        if (t < 768) {
            int nh = t & 1, rg = t >> 1;
            qt_task(rg / 96, rg % 96, nh, 96);
        } else if (t < 1024) {
            int t2 = t - 768;
            int g = t2 >> 6, rem = t2 & 63;
            kt_task(g, 32 + (rem >> 1), rem & 1);
        } else {
            int t3 = t - 1024;
            int g = t3 >> 3, n = t3 & 7;
            float sum = 0.f;
            #pragma unroll 8
            for (int c = 0; c < CL_; c++)
                sum += s->lq[(g * CL_ + c) * LPAD + n] * pe_b2[g * CL_ + c];
            s->bconst[g][n] = sum;
        }
    }
    __syncthreads();

    // ================= phase D1: spe(d>=96) + S_k(cc>=32, 8 per dq), accumulate =================
    {
        int dq = tid >> 7;
        int r = tid & 127, n = r >> 4, k = r & 15;
        float rx = s->rel[n][k][0], ry = s->rel[n][k][1], rz = s->rel[n][k][2];
        float a0 = 0.f, a1 = 0.f, a2 = 0.f, a3 = 0.f;
        #pragma unroll 4
        for (int dd = 0; dd < 24; dd++) {
            int dloc = dq * 24 + dd;
            float4 wp = g_w1pack[96 + dloc];
            float hv = rx * wp.x + ry * wp.y + rz * wp.z + wp.w;
            hv = hv > 0.f ? hv : 0.f;
            hv = tf32r(hv);
            float4 q4 = *(const float4*)&s->qt[dloc * QPAD + n * 4];
            a0 += q4.x * hv; a1 += q4.y * hv; a2 += q4.z * hv; a3 += q4.w * hv;
        }
        #pragma unroll 4
        for (int cc = 32 + dq * 8; cc < 32 + dq * 8 + 8; cc++) {  // cc 32..63 (kt from C1)
            float xsv = tf32r(s->x[cc * XPAD + n * 16 + k]
                            + s->x[(cc + 64) * XPAD + n * 16 + k]);
            float4 k4 = *(const float4*)&s->kt[cc * QPAD + n * 4];
            a0 += k4.x * xsv; a1 += k4.y * xsv; a2 += k4.z * xsv; a3 += k4.w * xsv;
        }
        s->part[dq][0][n][k] += a0; s->part[dq][1][n][k] += a1;
        s->part[dq][2][n][k] += a2; s->part[dq][3][n][k] += a3;
    }
    __syncthreads();

    // ================= phase E: combine + softmax (32 tasks) =================
    if (tid < G_ * TN) {
        int g = tid >> 3, n = tid & 7;
        float sc[K_];
        float m = -1e30f;
        #pragma unroll
        for (int k = 0; k < K_; k++) {
            sc[k] = s->part[0][g][n][k] + s->part[1][g][n][k]
                  + s->part[2][g][n][k] + s->part[3][g][n][k] + s->bconst[g][n];
            m = fmaxf(m, sc[k]);
        }
        float sum = 0.f;
        #pragma unroll
        for (int k = 0; k < K_; k++) { sc[k] = expf(sc[k] - m); sum += sc[k]; }
        float inv = 1.f / sum;
        #pragma unroll
        for (int k = 0; k < K_; k++) s->att[g][n][k] = sc[k] * inv;
    }
    __syncthreads();

    // ================= phase F: scatter (1 atomic/thread) + xa =================
    {
        {
            int g = tid >> 7, rem = tid & 127, n = rem >> 4, k = rem & 15;
            atomicAdd(&g_cent[(b * G_ + g) * N_ + s->idxs[n][k]], s->att[g][n][k]);
        }
        float* xa = &s->qt[0];   // overlays qt+kt+lq (32256B >= 512*12*4=24576B)
        int cc = tid & 127, nset = tid >> 7;              // nset 0..3, 2 n each
        for (int ni = 0; ni < 2; ni++) {
            int n = nset * 2 + ni;
            float a0 = 0.f, a1 = 0.f, a2 = 0.f, a3 = 0.f;
            #pragma unroll
            for (int k = 0; k < K_; k++) {
                float xv = tf32r(s->x[cc * XPAD + n * 16 + k]);
                a0 += tf32r(s->att[0][n][k]) * xv;
                a1 += tf32r(s->att[1][n][k]) * xv;
                a2 += tf32r(s->att[2][n][k]) * xv;
                a3 += tf32r(s->att[3][n][k]) * xv;
            }
            xa[(0 * CIN_ + cc) * XAPAD + n] = a0;
            xa[(1 * CIN_ + cc) * XAPAD + n] = a1;
            xa[(2 * CIN_ + cc) * XAPAD + n] = a2;
            xa[(3 * CIN_ + cc) * XAPAD + n] = a3;
        }
    }
    __syncthreads();

    // ================= phase G: out = Wv^T-dot(xa) (384 thr, 4n each) + direct store =================
    if (tid < 384) {
        const float* xa = &s->qt[0];
        int o = tid % 192, nh = tid / 192;
        int g = o / CL_;
        float a0 = 0.f, a1 = 0.f, a2 = 0.f, a3 = 0.f;
        #pragma unroll 8
        for (int cc = 0; cc < CIN_; cc++) {
            float w = rT_Wv[cc * L_ + o];
            float4 xv = *(const float4*)&xa[(g * CIN_ + cc) * XAPAD + nh * 4];
            a0 += w * xv.x; a1 += w * xv.y; a2 += w * xv.z; a3 += w * xv.w;
        }
        *(float4*)&out[((size_t)(b * COUT_ + o)) * N_ + n0 + nh * 4] =
            make_float4(a0, a1, a2, a3);
    }
}

// ---------------- kernel 2: top-16 per (b,g), desc, tie -> lower index ----------------
__global__ __launch_bounds__(256) void k_topk() {
    const int bg  = blockIdx.x;
    const int tid = threadIdx.x;
    const int lane = tid & 31, warp = tid >> 5;
    __shared__ float v_s[N_];
    __shared__ float wvv[8];
    __shared__ int   wii[8];

    for (int i = tid; i < N_; i += 256) v_s[i] = g_cent[bg * N_ + i];
    __syncthreads();

    for (int t = 0; t < K_; t++) {
        float bv = -1e30f; int bi = N_;
        for (int i = tid; i < N_; i += 256) {
            float v = v_s[i];
            if (v > bv || (v == bv && i < bi)) { bv = v; bi = i; }
        }
        #pragma unroll
        for (int off = 16; off > 0; off >>= 1) {
            float ov = __shfl_down_sync(0xffffffffu, bv, off);
            int   oi = __shfl_down_sync(0xffffffffu, bi, off);
            if (ov > bv || (ov == bv && oi < bi)) { bv = ov; bi = oi; }
        }
        if (lane == 0) { wvv[warp] = bv; wii[warp] = bi; }
        __syncthreads();
        if (tid < 32) {
            float v2 = (tid < 8) ? wvv[tid] : -1e30f;
            int   i2 = (tid < 8) ? wii[tid] : N_;
            #pragma unroll
            for (int off = 4; off > 0; off >>= 1) {
                float ov = __shfl_down_sync(0xffffffffu, v2, off);
                int   oi = __shfl_down_sync(0xffffffffu, i2, off);
                if (ov > v2 || (ov == v2 && oi < i2)) { v2 = ov; i2 = oi; }
            }
            if (tid == 0) {
                g_vals[bg * K_ + t] = v2;
                g_inds[bg * K_ + t] = i2;
                v_s[i2] = -1e30f;
            }
        }
        __syncthreads();
    }
}

// ---------------- kernel 3: non-local prep per (b,g), smem-staged gathers ----------------
__global__ __launch_bounds__(256) void k_nl_prep(
    const float* __restrict__ abs_x,
    const float* __restrict__ points,
    const float* __restrict__ npe_b1,
    const float* __restrict__ npe_b2)
{
    const int bg = blockIdx.x;
    const int b = bg / G_, g = bg % G_;
    const int tid = threadIdx.x;

    __shared__ int   inds_s[K_];
    __shared__ float rel_s[3][K_];
    __shared__ float h2_s[K_][CNL_];
    __shared__ float a2g[K_][65];     // gathered tf32r(abs_x) at selected indices

    if (tid < K_) {
        inds_s[tid] = g_inds[bg * K_ + tid];
        g_tanhvals[bg * K_ + tid] = tanhf(g_vals[bg * K_ + tid]);
    }
    __syncthreads();
    // gather abs_x columns for the 16 selected n (4 LDG per thread)
    for (int i = tid; i < K_ * 64; i += 256) {
        int j = i >> 6, cc = i & 63;
        a2g[j][cc] = tf32r(abs_x[(b * 64 + cc) * N_ + inds_s[j]]);
    }
    if (tid < 3 * K_) {
        int c = tid / K_, j = tid % K_;
        rel_s[c][j] = tf32r(points[(b * 3 + c) * N_ + inds_s[j]]
                          - points[(b * 3 + c) * N_ + inds_s[0]]);
    }
    __syncthreads();
    {
        int j = tid / CNL_, d = tid % CNL_;
        float h = npe_b1[g * CNL_ + d];
        #pragma unroll
        for (int c = 0; c < 3; c++) h += rel_s[c][j] * r_npe_w1[(g * 3 + c) * CNL_ + d];
        h2_s[j][d] = tf32r(h > 0.f ? h : 0.f);
    }
    __syncthreads();
    {
        int c = tid / K_, j = tid % K_;
        float pe = npe_b2[g * CNL_ + c];
        #pragma unroll
        for (int d = 0; d < CNL_; d++) pe += h2_s[j][d] * r_npe_w2[(g * CNL_ + d) * CNL_ + c];
        float nk = 0.f, nv2 = 0.f;
        const int row = g * CNL_ + c;
        #pragma unroll 8
        for (int cc = 0; cc < 64; cc++) {
            float a = a2g[j][cc];
            nk  += rT_Wnk[cc * NL_ + row]  * a;
            nv2 += rT_Wnv2[cc * NL_ + row] * a;
        }
        g_M[bg * CNL_ * K_ + c * K_ + j]    = nk + pe;
        g_nv2j[bg * CNL_ * K_ + c * K_ + j] = nv2;
    }
}

// ---------------- kernel 4: non-local main (full a2 preload, barrier-free loop) ----------------
struct __align__(16) NLSmem {
    float wnq[64 * 64];
    float wnv1[64 * 64];
    float wnv2[64 * 64];
    float M[G_][CNL_ * K_];
    float nv2jT[G_][K_ * CNL_];
    float tv[G_ * K_];
    float a2[64][TNL];           // [cc][n_local], 16 KB
    float outbuf[64 * 65];
};                               // ~90.6 KB -> 2 CTA/SM

__global__ __launch_bounds__(256) void k_nl_main(
    const float* __restrict__ abs_x,
    float*       __restrict__ out)
{
    extern __shared__ char smraw[];
    NLSmem* s = (NLSmem*)smraw;

    const int blk = blockIdx.x;
    const int b   = blk / (N_ / TNL);
    const int n0  = (blk % (N_ / TNL)) * TNL;
    const int tid = threadIdx.x;
    const int warp  = tid >> 5;
    const int half  = (tid >> 4) & 1;
    const int c     = tid & 15;
    const int g     = (warp & 1) * 2 + half;
    const int nslot = warp >> 1;
    const int o     = g * CNL_ + c;

    for (int i = tid; i < 64 * 64; i += 256) {
        s->wnq[i]  = rT_Wnq[i];
        s->wnv1[i] = rT_Wnv1[i];
        s->wnv2[i] = rT_Wnv2[i];
    }
    for (int i = tid; i < 64 * TNL; i += 256) {   // coalesced a2 preload
        int cc = i >> 6, n = i & 63;
        s->a2[cc][n] = tf32r(abs_x[(b * 64 + cc) * N_ + n0 + n]);
    }
    for (int i = tid; i < G_ * CNL_ * K_; i += 256) {
        float mv = tf32r(g_M[b * G_ * CNL_ * K_ + i]);
        s->M[0][i] = mv;
        int gg = i >> 8, rem = i & 255, cc2 = rem >> 4, jj = rem & 15;
        s->nv2jT[gg][jj * 16 + cc2] = tf32r(g_nv2j[b * G_ * CNL_ * K_ + i]);
    }
    if (tid < G_ * K_) s->tv[tid] = g_tanhvals[b * G_ * K_ + tid];
    __syncthreads();

    const float tvj = s->tv[g * K_ + c];

    for (int it = 0; it < TNL / 4; it++) {
        const int nn = it * 4 + nslot;

        float nq = 0.f, nv1 = 0.f, nv2 = 0.f;
        #pragma unroll 8
        for (int cc = 0; cc < 64; cc++) {
            float a = s->a2[cc][nn];
            nq  += s->wnq[cc * 64 + o]  * a;
            nv1 += s->wnv1[cc * 64 + o] * a;
            nv2 += s->wnv2[cc * 64 + o] * a;
        }
        float nqr = tf32r(nq);

        float sc = 0.f;
        const float* Mg = s->M[g];
        #pragma unroll
        for (int c2 = 0; c2 < CNL_; c2++) {
            float v = __shfl_sync(0xffffffffu, nqr, c2, 16);
            sc += v * Mg[c2 * 16 + c];
        }
        float m = -1e30f;
        #pragma unroll
        for (int j = 0; j < K_; j++) m = fmaxf(m, __shfl_sync(0xffffffffu, sc, j, 16));
        float e = expf(sc - m);
        float sum = 0.f;
        #pragma unroll
        for (int j = 0; j < K_; j++) sum += __shfl_sync(0xffffffffu, e, j, 16);
        float inv = 1.f / sum;
        float w = e * inv * tvj;
        float ws = 0.f;
        #pragma unroll
        for (int j = 0; j < K_; j++) ws += __shfl_sync(0xffffffffu, w, j, 16);

        float og = (nv1 - nv2) * ws;
        const float* nvg = s->nv2jT[g];
        #pragma unroll
        for (int j = 0; j < K_; j++) {
            float wj = tf32r(__shfl_sync(0xffffffffu, w, j, 16));
            og += wj * nvg[j * 16 + c];
        }
        s->outbuf[o * 65 + nn] = og;
    }
    __syncthreads();

    for (int t = tid; t < 64 * 16; t += 256) {
        int o2 = t >> 4, q = t & 15;
        const float* rp = &s->outbuf[o2 * 65 + q * 4];
        float4 v = make_float4(rp[0], rp[1], rp[2], rp[3]);
        *(float4*)&out[((size_t)(b * COUT_ + L_ + o2)) * N_ + n0 + q * 4] = v;
    }
}

// ---------------- launcher ----------------
extern "C" void kernel_launch(void* const* d_in, const int* in_sizes, int n_in,
                              void* d_out, int out_size) {
    const float* x      = (const float*)d_in[0];
    const float* abs_x  = (const float*)d_in[1];
    const float* points = (const float*)d_in[2];
    const float* Wq     = (const float*)d_in[3];
    const float* Wk     = (const float*)d_in[4];
    const float* Wv     = (const float*)d_in[5];
    const float* Wnq    = (const float*)d_in[6];
    const float* Wnk    = (const float*)d_in[7];
    const float* Wnv1   = (const float*)d_in[8];
    const float* Wnv2   = (const float*)d_in[9];
    const float* pe_w1  = (const float*)d_in[10];
    const float* pe_b1  = (const float*)d_in[11];
    const float* pe_w2  = (const float*)d_in[12];
    const float* pe_b2  = (const float*)d_in[13];
    const float* npe_w1 = (const float*)d_in[14];
    const float* npe_b1 = (const float*)d_in[15];
    const float* npe_w2 = (const float*)d_in[16];
    const float* npe_b2 = (const float*)d_in[17];
    const int*   idx    = (const int*)d_in[18];
    float* out = (float*)d_out;

    static int smem_set = 0;
    if (!smem_set) {
        cudaFuncSetAttribute(k_local, cudaFuncAttributeMaxDynamicSharedMemorySize,
                             (int)sizeof(LocalSmem));
        cudaFuncSetAttribute(k_nl_main, cudaFuncAttributeMaxDynamicSharedMemorySize,
                             (int)sizeof(NLSmem));
        smem_set = 1;
    }

    k_prep<<<128, 256>>>(Wq, Wk, Wv, pe_w1, pe_b1, pe_w2,
                         Wnq, Wnk, Wnv1, Wnv2, npe_w1, npe_w2);
    k_local<<<B_ * (N_ / TN), THR, sizeof(LocalSmem)>>>(x, abs_x, points,
                                                        pe_b2, idx, out);
    k_topk<<<B_ * G_, 256>>>();
    k_nl_prep<<<B_ * G_, 256>>>(abs_x, points, npe_b1, npe_b2);
    k_nl_main<<<B_ * (N_ / TNL), 256, sizeof(NLSmem)>>>(abs_x, out);
}